// round 16
// baseline (speedup 1.0000x reference)
#include <cuda_runtime.h>
#include <cuda_fp16.h>

#define N_NODES 100000
#define N_EDGES 1600000
#define IN_DIM  256
#define HID     128
#define OUT_DIM 40
#define SCAN_BS 1024
#define NB_SCAN ((N_NODES + SCAN_BS - 1) / SCAN_BS)

typedef unsigned long long u64;
typedef unsigned int u32;

// ---- scratch ----
__device__ float g_deg[N_NODES];
__device__ float g_isd[N_NODES];
__device__ __align__(16) __half g_h1[(size_t)N_NODES * HID];     // fp16 x@W1
__device__ __align__(16) __half g_a1[(size_t)N_NODES * HID];     // relu(isd*agg+b1)
__device__ __align__(16) __half g_h2[(size_t)N_NODES * OUT_DIM]; // fp16 layer2
__device__ __align__(16) __half g_W1h[HID * IN_DIM];             // fp16(W1), [n][k]
__device__ __align__(16) __half g_W2h[OUT_DIM * HID];            // fp16 hi(W2), [n][k]
__device__ __align__(16) __half g_W2l[OUT_DIM * HID];            // fp16 lo(W2), [n][k]
__device__ int g_rowstart[N_NODES + 1];
__device__ int g_cursor[N_NODES];
__device__ int g_bsum[NB_SCAN];
__device__ int g_elist[N_EDGES];

// ---------------------------------------------------------------- degree ----
__global__ void k_zero_deg(int n) {
    int i = blockIdx.x * blockDim.x + threadIdx.x;
    if (i < n) g_deg[i] = 0.f;
}
__global__ void k_count(const int* __restrict__ dst, int e) {
    int i = blockIdx.x * blockDim.x + threadIdx.x;
    if (i < e) atomicAdd(&g_deg[dst[i]], 1.0f);
}

// ---------------------------------------------- CSR build (+ isd in scan1) --
__global__ void k_scan1(int n) {
    __shared__ int sm[SCAN_BS];
    int t = threadIdx.x;
    int idx = blockIdx.x * SCAN_BS + t;
    int v = (idx < n) ? (int)g_deg[idx] : 0;
    if (idx < n)
        g_isd[idx] = (v > 0) ? rsqrtf((float)v) : 0.f;
    sm[t] = v;
    __syncthreads();
    #pragma unroll
    for (int off = 1; off < SCAN_BS; off <<= 1) {
        int y = (t >= off) ? sm[t - off] : 0;
        __syncthreads();
        sm[t] += y;
        __syncthreads();
    }
    if (idx < n) g_rowstart[idx] = sm[t] - v;
    if (t == SCAN_BS - 1) g_bsum[blockIdx.x] = sm[t];
}
__global__ void k_scan2(int n, int e) {
    if (threadIdx.x == 0) {
        int run = 0;
        for (int i = 0; i < NB_SCAN; i++) {
            int t = g_bsum[i];
            g_bsum[i] = run;
            run += t;
        }
        g_rowstart[n] = run;
    }
}
__global__ void k_scan3(int n) {
    int i = blockIdx.x * blockDim.x + threadIdx.x;
    if (i < n) {
        int rs = g_rowstart[i] + g_bsum[i >> 10];
        g_rowstart[i] = rs;
        g_cursor[i] = rs;
    }
}
__global__ void k_scatter(const int* __restrict__ src, const int* __restrict__ dst, int e) {
    int i = blockIdx.x * blockDim.x + threadIdx.x;
    if (i < e) {
        int pos = atomicAdd(&g_cursor[dst[i]], 1);
        g_elist[pos] = src[i];
    }
}

// ---------------------------------------- W1 fp16, W2 hi/lo fp16, [n][k] ----
__global__ void k_splitW(const float* __restrict__ W1, const float* __restrict__ W2) {
    int i = blockIdx.x * blockDim.x + threadIdx.x;
    if (i < HID * IN_DIM) {
        int n = i & (HID - 1), k = i >> 7;
        g_W1h[n * IN_DIM + k] = __float2half(W1[(size_t)k * HID + n]);
    }
    if (i < OUT_DIM * HID) {
        int n2 = i % OUT_DIM, k2 = i / OUT_DIM;
        float v = W2[k2 * OUT_DIM + n2];
        __half h = __float2half(v);
        __half lo = __float2half(v - __half2float(h));
        g_W2h[n2 * HID + k2] = h;
        g_W2l[n2 * HID + k2] = lo;
    }
}

// -------------------------------------------------------------- HMMA GEMM1 --
#define A_H    0
#define B_H    8192
#define AB_STRIDE 24576
#define SMEM_G1 (2 * AB_STRIDE)   // 48 KB

__device__ __forceinline__ u32 toff(int r, int cb) {
    return (u32)((r >> 3) * 1024 + (r & 7) * 128 + (cb ^ ((r & 7) << 4)));
}
__device__ __forceinline__ void ldsm4(u32* r, u32 addr) {
    asm volatile("ldmatrix.sync.aligned.m8n8.x4.shared.b16 {%0,%1,%2,%3}, [%4];"
                 : "=r"(r[0]), "=r"(r[1]), "=r"(r[2]), "=r"(r[3]) : "r"(addr));
}
__device__ __forceinline__ void mma16816(float* c, const u32* a, const u32* b) {
    asm volatile(
        "mma.sync.aligned.m16n8k16.row.col.f32.f16.f16.f32 "
        "{%0,%1,%2,%3}, {%4,%5,%6,%7}, {%8,%9}, {%0,%1,%2,%3};"
        : "+f"(c[0]), "+f"(c[1]), "+f"(c[2]), "+f"(c[3])
        : "r"(a[0]), "r"(a[1]), "r"(a[2]), "r"(a[3]), "r"(b[0]), "r"(b[1]));
}

__global__ void __launch_bounds__(256, 2)
k_gemm1(const float* __restrict__ x, int n) {
    extern __shared__ char smem[];
    u32 sb;
    asm("{ .reg .u64 t; cvta.to.shared.u64 t, %1; cvt.u32.u64 %0, t; }"
        : "=r"(sb) : "l"(smem));
    const int tid = threadIdx.x;
    const int l = tid & 31;
    const int wid = tid >> 5;
    const int wm = wid & 1;
    const int wn = wid >> 1;
    const int m0 = blockIdx.x * 64;

    float4 ra[4];
    uint4 rbh[4];

    #pragma unroll
    for (int j = 0; j < 4; j++) {
        int u = tid + j * 256;
        int r = u >> 4, kq = (u & 15) * 4;
        int row = m0 + r;
        ra[j] = (row < n) ? *(const float4*)&x[(size_t)row * IN_DIM + kq]
                          : make_float4(0.f, 0.f, 0.f, 0.f);
    }
    #pragma unroll
    for (int j = 0; j < 4; j++) {
        int u = tid + j * 256;
        int r = u >> 3, kq = (u & 7) * 8;
        rbh[j] = *(const uint4*)&g_W1h[r * IN_DIM + kq];
    }

    #pragma unroll
    for (int j = 0; j < 4; j++) {
        int u = tid + j * 256;
        int r = u >> 4, kq = (u & 15) * 4;
        float4 v = ra[j];
        __half2 p0 = __floats2half2_rn(v.x, v.y);
        __half2 p1 = __floats2half2_rn(v.z, v.w);
        *(uint2*)(smem + A_H + toff(r, kq * 2)) = make_uint2(*(u32*)&p0, *(u32*)&p1);
    }
    #pragma unroll
    for (int j = 0; j < 4; j++) {
        int u = tid + j * 256;
        int r = u >> 3, kq = (u & 7) * 8;
        *(uint4*)(smem + B_H + toff(r, kq * 2)) = rbh[j];
    }
    __syncthreads();

    float acc[2][4][4] = {};

    u32 PA[2], XA[2];
    #pragma unroll
    for (int mb = 0; mb < 2; mb++) {
        int r = wm * 32 + mb * 16 + (l & 7) + 8 * ((l >> 3) & 1);
        PA[mb] = (u32)((r >> 3) * 1024 + (r & 7) * 128);
        XA[mb] = (u32)((r & 7) << 4);
    }
    u32 cblA = 16 * (l >> 4);
    u32 PB[2], XB[2];
    #pragma unroll
    for (int nb = 0; nb < 2; nb++) {
        int r = wn * 32 + nb * 16 + (l & 7) + 8 * ((l >> 4) & 1);
        PB[nb] = (u32)((r >> 3) * 1024 + (r & 7) * 128);
        XB[nb] = (u32)((r & 7) << 4);
    }
    u32 cblB = 16 * ((l >> 3) & 1);

    #pragma unroll 1
    for (int ch = 0; ch < 4; ch++) {
        u32 base = sb + (u32)(ch & 1) * AB_STRIDE;

        if (ch < 3) {
            int k0 = (ch + 1) * 64;
            #pragma unroll
            for (int j = 0; j < 4; j++) {
                int u = tid + j * 256;
                int r = u >> 4, kq = (u & 15) * 4;
                int row = m0 + r;
                ra[j] = (row < n) ? *(const float4*)&x[(size_t)row * IN_DIM + k0 + kq]
                                  : make_float4(0.f, 0.f, 0.f, 0.f);
            }
            #pragma unroll
            for (int j = 0; j < 4; j++) {
                int u = tid + j * 256;
                int r = u >> 3, kq = (u & 7) * 8;
                rbh[j] = *(const uint4*)&g_W1h[r * IN_DIM + k0 + kq];
            }
        }

        #pragma unroll
        for (int ks = 0; ks < 4; ks++) {
            u32 kb = ks * 32;
            u32 Ah[2][4], Bf[2][4];
            #pragma unroll
            for (int mb = 0; mb < 2; mb++)
                ldsm4(Ah[mb], base + A_H + PA[mb] + ((kb + cblA) ^ XA[mb]));
            #pragma unroll
            for (int nb = 0; nb < 2; nb++)
                ldsm4(Bf[nb], base + B_H + PB[nb] + ((kb + cblB) ^ XB[nb]));
            #pragma unroll
            for (int mb = 0; mb < 2; mb++)
                #pragma unroll
                for (int nb = 0; nb < 2; nb++)
                    #pragma unroll
                    for (int j = 0; j < 2; j++)
                        mma16816(acc[mb][nb * 2 + j], Ah[mb], &Bf[nb][2 * j]);
        }

        if (ch < 3) {
            char* nb_ = smem + ((ch + 1) & 1) * AB_STRIDE;
            #pragma unroll
            for (int j = 0; j < 4; j++) {
                int u = tid + j * 256;
                int r = u >> 4, kq = (u & 15) * 4;
                float4 v = ra[j];
                __half2 p0 = __floats2half2_rn(v.x, v.y);
                __half2 p1 = __floats2half2_rn(v.z, v.w);
                *(uint2*)(nb_ + A_H + toff(r, kq * 2)) =
                    make_uint2(*(u32*)&p0, *(u32*)&p1);
            }
            #pragma unroll
            for (int j = 0; j < 4; j++) {
                int u = tid + j * 256;
                int r = u >> 3, kq = (u & 7) * 8;
                *(uint4*)(nb_ + B_H + toff(r, kq * 2)) = rbh[j];
            }
            __syncthreads();
        }
    }

    #pragma unroll
    for (int mb = 0; mb < 2; mb++) {
        int r0 = m0 + wm * 32 + mb * 16 + (l >> 2);
        int r1 = r0 + 8;
        #pragma unroll
        for (int idx = 0; idx < 4; idx++) {
            int col = wn * 32 + idx * 8 + (l & 3) * 2;
            float* c = acc[mb][idx];
            if (r0 < n) {
                __half2 p = __floats2half2_rn(c[0], c[1]);
                *(u32*)&g_h1[(size_t)r0 * HID + col] = *(u32*)&p;
            }
            if (r1 < n) {
                __half2 p = __floats2half2_rn(c[2], c[3]);
                *(u32*)&g_h1[(size_t)r1 * HID + col] = *(u32*)&p;
            }
        }
    }
}

// ------------------------------------------------- layer1 CSR aggregation ---
// Warp per node, half-warp edge split, software-pipelined batches of 4:
// indices+isd of batch k+1 load while batch k's h1-gathers are in flight.
__global__ void k_agg1(const float* __restrict__ b1, int n) {
    int gid = blockIdx.x * blockDim.x + threadIdx.x;
    int node = gid >> 5;
    int lane = threadIdx.x & 31;
    if (node >= n) return;
    int half = lane >> 4, fl = lane & 15;

    const uint4* h1 = (const uint4*)g_h1;
    float acc[8] = {};
    int beg = g_rowstart[node];
    int end = g_rowstart[node + 1];
    #define ACC_E(uu, qq) { \
        float2 a0 = __half22float2(*(__half2*)&uu.x); \
        float2 a1_ = __half22float2(*(__half2*)&uu.y); \
        float2 a2 = __half22float2(*(__half2*)&uu.z); \
        float2 a3 = __half22float2(*(__half2*)&uu.w); \
        acc[0] = fmaf(qq, a0.x, acc[0]); acc[1] = fmaf(qq, a0.y, acc[1]); \
        acc[2] = fmaf(qq, a1_.x, acc[2]); acc[3] = fmaf(qq, a1_.y, acc[3]); \
        acc[4] = fmaf(qq, a2.x, acc[4]); acc[5] = fmaf(qq, a2.y, acc[5]); \
        acc[6] = fmaf(qq, a3.x, acc[6]); acc[7] = fmaf(qq, a3.y, acc[7]); }

    int j = beg + half;
    int s_[4]; float q_[4];
    if (j + 6 < end) {
        #pragma unroll
        for (int t = 0; t < 4; t++) s_[t] = g_elist[j + 2 * t];
        #pragma unroll
        for (int t = 0; t < 4; t++) q_[t] = __ldg(&g_isd[s_[t]]);
    }
    while (j + 6 < end) {
        uint4 u[4];
        #pragma unroll
        for (int t = 0; t < 4; t++) u[t] = h1[(size_t)s_[t] * 16 + fl];
        int jn = j + 8;
        if (jn + 6 < end) {
            int sN[4];
            #pragma unroll
            for (int t = 0; t < 4; t++) sN[t] = g_elist[jn + 2 * t];
            float qN[4];
            #pragma unroll
            for (int t = 0; t < 4; t++) qN[t] = __ldg(&g_isd[sN[t]]);
            #pragma unroll
            for (int t = 0; t < 4; t++) ACC_E(u[t], q_[t])
            #pragma unroll
            for (int t = 0; t < 4; t++) { s_[t] = sN[t]; q_[t] = qN[t]; }
        } else {
            #pragma unroll
            for (int t = 0; t < 4; t++) ACC_E(u[t], q_[t])
        }
        j = jn;
    }
    for (; j < end; j += 2) {
        int s = g_elist[j];
        float q = __ldg(&g_isd[s]);
        uint4 uu = h1[(size_t)s * 16 + fl];
        ACC_E(uu, q)
    }
    #undef ACC_E
    #pragma unroll
    for (int t = 0; t < 8; t++)
        acc[t] += __shfl_xor_sync(0xffffffffu, acc[t], 16);

    if (half == 0) {
        float sd = g_isd[node];
        float4 blo = *(const float4*)&b1[fl * 8];
        float4 bhi = *(const float4*)&b1[fl * 8 + 4];
        float o0 = fmaxf(fmaf(sd, acc[0], blo.x), 0.f);
        float o1 = fmaxf(fmaf(sd, acc[1], blo.y), 0.f);
        float o2 = fmaxf(fmaf(sd, acc[2], blo.z), 0.f);
        float o3 = fmaxf(fmaf(sd, acc[3], blo.w), 0.f);
        float o4 = fmaxf(fmaf(sd, acc[4], bhi.x), 0.f);
        float o5 = fmaxf(fmaf(sd, acc[5], bhi.y), 0.f);
        float o6 = fmaxf(fmaf(sd, acc[6], bhi.z), 0.f);
        float o7 = fmaxf(fmaf(sd, acc[7], bhi.w), 0.f);
        __half2 p0 = __floats2half2_rn(o0, o1);
        __half2 p1 = __floats2half2_rn(o2, o3);
        __half2 p2 = __floats2half2_rn(o4, o5);
        __half2 p3 = __floats2half2_rn(o6, o7);
        uint4 outv = make_uint4(*(u32*)&p0, *(u32*)&p1, *(u32*)&p2, *(u32*)&p3);
        ((uint4*)g_a1)[(size_t)node * 16 + fl] = outv;
    }
}

// -------------------------------------------------------------- HMMA GEMM2 --
#define G2_SA    0            // 2 chunks x 16384
#define G2_BH    32768        // 2 chunks x 6144
#define G2_BL    45056        // 2 chunks x 6144
#define SMEM_G2  57344

__global__ void __launch_bounds__(256)
k_gemm2(int n) {
    extern __shared__ char smem[];
    u32 sb;
    asm("{ .reg .u64 t; cvta.to.shared.u64 t, %1; cvt.u32.u64 %0, t; }"
        : "=r"(sb) : "l"(smem));
    const int tid = threadIdx.x;
    const int l = tid & 31;
    const int wm = tid >> 5;
    const int m0 = blockIdx.x * 128;

    #pragma unroll
    for (int j = 0; j < 8; j++) {
        int u = tid + j * 256;
        int r = u >> 4, k8 = (u & 15) * 8;
        int ch = k8 >> 6, w = k8 & 63;
        int row = m0 + r;
        uint4 v = make_uint4(0, 0, 0, 0);
        if (row < n) v = *(const uint4*)&g_a1[(size_t)row * HID + k8];
        *(uint4*)(smem + G2_SA + ch * 16384 + toff(r, w * 2)) = v;
    }
    #pragma unroll
    for (int j = 0; j < 3; j++) {
        int u = tid + j * 256;
        int r = u >> 4, k8 = (u & 15) * 8;
        int ch = k8 >> 6, w = k8 & 63;
        uint4 vh = make_uint4(0, 0, 0, 0), vl = make_uint4(0, 0, 0, 0);
        if (r < OUT_DIM) {
            vh = *(const uint4*)&g_W2h[r * HID + k8];
            vl = *(const uint4*)&g_W2l[r * HID + k8];
        }
        u32 off = toff(r, w * 2);
        *(uint4*)(smem + G2_BH + ch * 6144 + off) = vh;
        *(uint4*)(smem + G2_BL + ch * 6144 + off) = vl;
    }
    __syncthreads();

    float acc[3][8] = {};

    u32 PA, XA;
    {
        int r = wm * 16 + (l & 7) + 8 * ((l >> 3) & 1);
        PA = (u32)((r >> 3) * 1024 + (r & 7) * 128);
        XA = (u32)((r & 7) << 4);
    }
    u32 cblA = 16 * (l >> 4);
    u32 PB[3], XB[3];
    #pragma unroll
    for (int nt = 0; nt < 3; nt++) {
        int r = nt * 16 + (l & 7) + 8 * ((l >> 4) & 1);
        PB[nt] = (u32)((r >> 3) * 1024 + (r & 7) * 128);
        XB[nt] = (u32)((r & 7) << 4);
    }
    u32 cblB = 16 * ((l >> 3) & 1);

    #pragma unroll
    for (int ch = 0; ch < 2; ch++) {
        u32 baseA = sb + G2_SA + ch * 16384;
        u32 baseBh = sb + G2_BH + ch * 6144;
        u32 baseBl = sb + G2_BL + ch * 6144;
        #pragma unroll
        for (int ks = 0; ks < 4; ks++) {
            u32 kb = ks * 32;
            u32 Af[4], Bh[3][4], Bl[3][4];
            ldsm4(Af, baseA + PA + ((kb + cblA) ^ XA));
            #pragma unroll
            for (int nt = 0; nt < 3; nt++) {
                u32 boff = PB[nt] + ((kb + cblB) ^ XB[nt]);
                ldsm4(Bh[nt], baseBh + boff);
                ldsm4(Bl[nt], baseBl + boff);
            }
            #pragma unroll
            for (int nt = 0; nt < 3; nt++)
                #pragma unroll
                for (int j = 0; j < 2; j++) {
                    float* c = &acc[nt][4 * j];
                    mma16816(c, Af, &Bh[nt][2 * j]);
                    mma16816(c, Af, &Bl[nt][2 * j]);
                }
        }
    }

    int r0 = m0 + wm * 16 + (l >> 2);
    int r1 = r0 + 8;
    float s0 = (r0 < n) ? g_isd[r0] : 0.f;
    float s1 = (r1 < n) ? g_isd[r1] : 0.f;
    #pragma unroll
    for (int nt = 0; nt < 3; nt++)
        #pragma unroll
        for (int j = 0; j < 2; j++) {
            int col = nt * 16 + j * 8 + (l & 3) * 2;
            if (col < OUT_DIM) {
                float* c = &acc[nt][4 * j];
                if (r0 < n) {
                    __half2 p = __floats2half2_rn(c[0] * s0, c[1] * s0);
                    *(u32*)&g_h2[(size_t)r0 * OUT_DIM + col] = *(u32*)&p;
                }
                if (r1 < n) {
                    __half2 p = __floats2half2_rn(c[2] * s1, c[3] * s1);
                    *(u32*)&g_h2[(size_t)r1 * OUT_DIM + col] = *(u32*)&p;
                }
            }
        }
}

// -------------------------------------------------- layer2 CSR aggregation --
// thread per (node, uint4-chunk c<5); pipelined batches of 4 edges.
__global__ void k_agg2(const float* __restrict__ b2, float* __restrict__ out, int n) {
    int i = blockIdx.x * blockDim.x + threadIdx.x;
    if (i >= n * 5) return;
    int node = i / 5;
    int c = i - node * 5;
    int beg = g_rowstart[node];
    int end = g_rowstart[node + 1];
    const uint4* h2 = (const uint4*)g_h2;
    float acc[8] = {};
    #define ACC2(uu) { \
        float2 a0 = __half22float2(*(__half2*)&uu.x); \
        float2 a1_ = __half22float2(*(__half2*)&uu.y); \
        float2 a2 = __half22float2(*(__half2*)&uu.z); \
        float2 a3 = __half22float2(*(__half2*)&uu.w); \
        acc[0] += a0.x; acc[1] += a0.y; acc[2] += a1_.x; acc[3] += a1_.y; \
        acc[4] += a2.x; acc[5] += a2.y; acc[6] += a3.x; acc[7] += a3.y; }
    int j = beg;
    int s_[4];
    if (j + 4 <= end) {
        #pragma unroll
        for (int t = 0; t < 4; t++) s_[t] = g_elist[j + t];
    }
    while (j + 4 <= end) {
        uint4 u[4];
        #pragma unroll
        for (int t = 0; t < 4; t++) u[t] = h2[(size_t)s_[t] * 5 + c];
        int jn = j + 4;
        if (jn + 4 <= end) {
            int sN[4];
            #pragma unroll
            for (int t = 0; t < 4; t++) sN[t] = g_elist[jn + t];
            #pragma unroll
            for (int t = 0; t < 4; t++) ACC2(u[t])
            #pragma unroll
            for (int t = 0; t < 4; t++) s_[t] = sN[t];
        } else {
            #pragma unroll
            for (int t = 0; t < 4; t++) ACC2(u[t])
        }
        j = jn;
    }
    for (; j < end; j++) {
        int s = g_elist[j];
        uint4 uu = h2[(size_t)s * 5 + c];
        ACC2(uu)
    }
    #undef ACC2
    float sd = g_isd[node];
    float4 blo = *(const float4*)&b2[c * 8];
    float4 bhi = *(const float4*)&b2[c * 8 + 4];
    float* o = &out[(size_t)node * OUT_DIM + c * 8];
    *(float4*)&o[0] = make_float4(fmaf(sd, acc[0], blo.x), fmaf(sd, acc[1], blo.y),
                                  fmaf(sd, acc[2], blo.z), fmaf(sd, acc[3], blo.w));
    *(float4*)&o[4] = make_float4(fmaf(sd, acc[4], bhi.x), fmaf(sd, acc[5], bhi.y),
                                  fmaf(sd, acc[6], bhi.z), fmaf(sd, acc[7], bhi.w));
}

// ---------------------------------------------------------------- launch ----
extern "C" void kernel_launch(void* const* d_in, const int* in_sizes, int n_in,
                              void* d_out, int out_size) {
    const float* x   = (const float*)d_in[0];
    const int*   src = (const int*)d_in[1];
    const int*   dst = (const int*)d_in[2];
    const float* W1  = (const float*)d_in[3];
    const float* b1  = (const float*)d_in[4];
    const float* W2  = (const float*)d_in[5];
    const float* b2  = (const float*)d_in[6];
    float* out = (float*)d_out;

    int n = in_sizes[0] / IN_DIM;
    int e = in_sizes[1];

    static cudaStream_t s_side = 0;
    static cudaEvent_t e_fork = 0, e_join = 0;
    if (!s_side) {
        cudaFuncSetAttribute(k_gemm1, cudaFuncAttributeMaxDynamicSharedMemorySize,
                             SMEM_G1);
        cudaFuncSetAttribute(k_gemm2, cudaFuncAttributeMaxDynamicSharedMemorySize,
                             SMEM_G2);
        cudaStreamCreateWithFlags(&s_side, cudaStreamNonBlocking);
        cudaEventCreateWithFlags(&e_fork, cudaEventDisableTiming);
        cudaEventCreateWithFlags(&e_join, cudaEventDisableTiming);
    }

    // k_gemm1 stays the 4th submission (ncu -s 5 -c 1 captures it).
    k_splitW<<<(HID * IN_DIM + 255) / 256, 256>>>(W1, W2);          // 1 (main)

    cudaEventRecord(e_fork, 0);
    cudaStreamWaitEvent(s_side, e_fork, 0);
    k_zero_deg<<<(n + 255) / 256, 256, 0, s_side>>>(n);             // 2
    k_count<<<(e + 255) / 256, 256, 0, s_side>>>(dst, e);           // 3

    k_gemm1<<<(n + 63) / 64, 256, SMEM_G1>>>(x, n);                 // 4 (main)

    k_scan1<<<NB_SCAN, SCAN_BS, 0, s_side>>>(n);                    // 5 (+isd)
    k_scan2<<<1, 32, 0, s_side>>>(n, e);                            // 6
    k_scan3<<<(n + 255) / 256, 256, 0, s_side>>>(n);                // 7
    k_scatter<<<(e + 255) / 256, 256, 0, s_side>>>(src, dst, e);    // 8
    cudaEventRecord(e_join, s_side);

    cudaStreamWaitEvent(0, e_join, 0);
    k_agg1<<<((n * 32) + 255) / 256, 256>>>(b1, n);                 // 9
    k_gemm2<<<(n + 127) / 128, 256, SMEM_G2>>>(n);                  // 10
    k_agg2<<<(n * 5 + 255) / 256, 256>>>(b2, out, n);               // 11
}

// round 17
// speedup vs baseline: 1.0512x; 1.0512x over previous
#include <cuda_runtime.h>
#include <cuda_fp16.h>

#define N_NODES 100000
#define N_EDGES 1600000
#define IN_DIM  256
#define HID     128
#define OUT_DIM 40
#define SCAN_BS 1024
#define NB_SCAN ((N_NODES + SCAN_BS - 1) / SCAN_BS)

typedef unsigned long long u64;
typedef unsigned int u32;

// ---- scratch ----
__device__ float g_deg[N_NODES];
__device__ float g_isd[N_NODES];
__device__ __align__(16) __half g_h1[(size_t)N_NODES * HID];     // fp16 x@W1
__device__ __align__(16) __half g_a1[(size_t)N_NODES * HID];     // relu(isd*agg+b1)
__device__ __align__(16) __half g_h2[(size_t)N_NODES * OUT_DIM]; // fp16 layer2
__device__ __align__(16) __half g_W1h[HID * IN_DIM];             // fp16(W1), [n][k]
__device__ __align__(16) __half g_W2h[OUT_DIM * HID];            // fp16 hi(W2), [n][k]
__device__ __align__(16) __half g_W2l[OUT_DIM * HID];            // fp16 lo(W2), [n][k]
__device__ int g_rowstart[N_NODES + 1];
__device__ int g_cursor[N_NODES];
__device__ int g_bsum[NB_SCAN];
__device__ int g_elist[N_EDGES];

// ---------------------------------------------------------------- degree ----
__global__ void k_zero_deg(int n) {
    int i = blockIdx.x * blockDim.x + threadIdx.x;
    if (i < n) g_deg[i] = 0.f;
}
__global__ void k_count(const int* __restrict__ dst, int e) {
    int i = blockIdx.x * blockDim.x + threadIdx.x;
    if (i < e) atomicAdd(&g_deg[dst[i]], 1.0f);
}

// ---------------------------------------------- CSR build (+ isd in scan1) --
__global__ void k_scan1(int n) {
    __shared__ int sm[SCAN_BS];
    int t = threadIdx.x;
    int idx = blockIdx.x * SCAN_BS + t;
    int v = (idx < n) ? (int)g_deg[idx] : 0;
    if (idx < n)
        g_isd[idx] = (v > 0) ? rsqrtf((float)v) : 0.f;
    sm[t] = v;
    __syncthreads();
    #pragma unroll
    for (int off = 1; off < SCAN_BS; off <<= 1) {
        int y = (t >= off) ? sm[t - off] : 0;
        __syncthreads();
        sm[t] += y;
        __syncthreads();
    }
    if (idx < n) g_rowstart[idx] = sm[t] - v;
    if (t == SCAN_BS - 1) g_bsum[blockIdx.x] = sm[t];
}
__global__ void k_scan2(int n, int e) {
    if (threadIdx.x == 0) {
        int run = 0;
        for (int i = 0; i < NB_SCAN; i++) {
            int t = g_bsum[i];
            g_bsum[i] = run;
            run += t;
        }
        g_rowstart[n] = run;
    }
}
__global__ void k_scan3(int n) {
    int i = blockIdx.x * blockDim.x + threadIdx.x;
    if (i < n) {
        int rs = g_rowstart[i] + g_bsum[i >> 10];
        g_rowstart[i] = rs;
        g_cursor[i] = rs;
    }
}
__global__ void k_scatter(const int* __restrict__ src, const int* __restrict__ dst, int e) {
    int i = blockIdx.x * blockDim.x + threadIdx.x;
    if (i < e) {
        int pos = atomicAdd(&g_cursor[dst[i]], 1);
        g_elist[pos] = src[i];
    }
}

// ---------------------------------------- W1 fp16, W2 hi/lo fp16, [n][k] ----
__global__ void k_splitW(const float* __restrict__ W1, const float* __restrict__ W2) {
    int i = blockIdx.x * blockDim.x + threadIdx.x;
    if (i < HID * IN_DIM) {
        int n = i & (HID - 1), k = i >> 7;
        g_W1h[n * IN_DIM + k] = __float2half(W1[(size_t)k * HID + n]);
    }
    if (i < OUT_DIM * HID) {
        int n2 = i % OUT_DIM, k2 = i / OUT_DIM;
        float v = W2[k2 * OUT_DIM + n2];
        __half h = __float2half(v);
        __half lo = __float2half(v - __half2float(h));
        g_W2h[n2 * HID + k2] = h;
        g_W2l[n2 * HID + k2] = lo;
    }
}

// -------------------------------------------------------------- HMMA GEMM1 --
// h1 = x @ W1, single-pass fp16 (fp32 accum). BM=128, BN=128, 4Mx2N warps
// (warp tile m32 x n64 -> LDSM/MMA = 0.375). K chunks 64, double-buffered.
#define A_H    0
#define B_H    16384
#define AB_STRIDE 32768
#define SMEM_G1 (2 * AB_STRIDE)   // 64 KB

__device__ __forceinline__ u32 toff(int r, int cb) {
    return (u32)((r >> 3) * 1024 + (r & 7) * 128 + (cb ^ ((r & 7) << 4)));
}
__device__ __forceinline__ void ldsm4(u32* r, u32 addr) {
    asm volatile("ldmatrix.sync.aligned.m8n8.x4.shared.b16 {%0,%1,%2,%3}, [%4];"
                 : "=r"(r[0]), "=r"(r[1]), "=r"(r[2]), "=r"(r[3]) : "r"(addr));
}
__device__ __forceinline__ void mma16816(float* c, const u32* a, const u32* b) {
    asm volatile(
        "mma.sync.aligned.m16n8k16.row.col.f32.f16.f16.f32 "
        "{%0,%1,%2,%3}, {%4,%5,%6,%7}, {%8,%9}, {%0,%1,%2,%3};"
        : "+f"(c[0]), "+f"(c[1]), "+f"(c[2]), "+f"(c[3])
        : "r"(a[0]), "r"(a[1]), "r"(a[2]), "r"(a[3]), "r"(b[0]), "r"(b[1]));
}

__device__ __forceinline__ void stage_a1(char* dst, int tid, int m0, int k0,
                                         const float* __restrict__ x, int n) {
    #pragma unroll
    for (int j = 0; j < 8; j++) {
        int u = tid + j * 256;
        int r = u >> 4, kq = (u & 15) * 4;
        int row = m0 + r;
        float4 v = (row < n) ? *(const float4*)&x[(size_t)row * IN_DIM + k0 + kq]
                             : make_float4(0.f, 0.f, 0.f, 0.f);
        __half2 p0 = __floats2half2_rn(v.x, v.y);
        __half2 p1 = __floats2half2_rn(v.z, v.w);
        *(uint2*)(dst + A_H + toff(r, kq * 2)) = make_uint2(*(u32*)&p0, *(u32*)&p1);
    }
}

__global__ void __launch_bounds__(256, 2)
k_gemm1(const float* __restrict__ x, int n) {
    extern __shared__ char smem[];
    u32 sb;
    asm("{ .reg .u64 t; cvta.to.shared.u64 t, %1; cvt.u32.u64 %0, t; }"
        : "=r"(sb) : "l"(smem));
    const int tid = threadIdx.x;
    const int l = tid & 31;
    const int wid = tid >> 5;
    const int wm = wid & 3;        // 4 warps over M (32 rows each)
    const int wn = wid >> 2;       // 2 warps over N (64 cols each)
    const int m0 = blockIdx.x * 128;

    uint4 rbh[2];

    // prologue: stage chunk 0 (A convert, B copy)
    stage_a1(smem, tid, m0, 0, x, n);
    #pragma unroll
    for (int j = 0; j < 2; j++) {
        int u = tid + j * 256;
        int r = u >> 2, kq = (u & 3) * 16;
        rbh[j] = *(const uint4*)&g_W1h[r * IN_DIM + kq + 0];
        // second 8 halves of the 16-half strip
        *(uint4*)(smem + B_H + toff(r, (kq + 8) * 2)) =
            *(const uint4*)&g_W1h[r * IN_DIM + kq + 8];
        *(uint4*)(smem + B_H + toff(r, kq * 2)) = rbh[j];
    }
    __syncthreads();

    float acc[2][8][4] = {};

    u32 PA[2], XA[2];
    #pragma unroll
    for (int mb = 0; mb < 2; mb++) {
        int r = wm * 32 + mb * 16 + (l & 7) + 8 * ((l >> 3) & 1);
        PA[mb] = (u32)((r >> 3) * 1024 + (r & 7) * 128);
        XA[mb] = (u32)((r & 7) << 4);
    }
    u32 cblA = 16 * (l >> 4);
    u32 PB[4], XB[4];
    #pragma unroll
    for (int nt = 0; nt < 4; nt++) {
        int r = wn * 64 + nt * 16 + (l & 7) + 8 * ((l >> 4) & 1);
        PB[nt] = (u32)((r >> 3) * 1024 + (r & 7) * 128);
        XB[nt] = (u32)((r & 7) << 4);
    }
    u32 cblB = 16 * ((l >> 3) & 1);

    #pragma unroll 1
    for (int ch = 0; ch < 4; ch++) {
        u32 base = sb + (u32)(ch & 1) * AB_STRIDE;
        char* nbuf = smem + ((ch + 1) & 1) * AB_STRIDE;

        // MMA on current buffer
        #pragma unroll
        for (int ks = 0; ks < 4; ks++) {
            u32 kb = ks * 32;
            u32 Ah[2][4], Bf[4][4];
            #pragma unroll
            for (int mb = 0; mb < 2; mb++)
                ldsm4(Ah[mb], base + A_H + PA[mb] + ((kb + cblA) ^ XA[mb]));
            #pragma unroll
            for (int nt = 0; nt < 4; nt++)
                ldsm4(Bf[nt], base + B_H + PB[nt] + ((kb + cblB) ^ XB[nt]));
            #pragma unroll
            for (int mb = 0; mb < 2; mb++)
                #pragma unroll
                for (int nt = 0; nt < 4; nt++)
                    #pragma unroll
                    for (int j = 0; j < 2; j++)
                        mma16816(acc[mb][nt * 2 + j], Ah[mb], &Bf[nt][2 * j]);
        }

        // stage next chunk into other buffer
        if (ch < 3) {
            int k0 = (ch + 1) * 64;
            stage_a1(nbuf, tid, m0, k0, x, n);
            #pragma unroll
            for (int j = 0; j < 2; j++) {
                int u = tid + j * 256;
                int r = u >> 2, kq = (u & 3) * 16;
                *(uint4*)(nbuf + B_H + toff(r, kq * 2)) =
                    *(const uint4*)&g_W1h[r * IN_DIM + k0 + kq + 0];
                *(uint4*)(nbuf + B_H + toff(r, (kq + 8) * 2)) =
                    *(const uint4*)&g_W1h[r * IN_DIM + k0 + kq + 8];
            }
            __syncthreads();
        }
    }

    // epilogue: store h1 fp16
    #pragma unroll
    for (int mb = 0; mb < 2; mb++) {
        int r0 = m0 + wm * 32 + mb * 16 + (l >> 2);
        int r1 = r0 + 8;
        #pragma unroll
        for (int idx = 0; idx < 8; idx++) {
            int col = wn * 64 + idx * 8 + (l & 3) * 2;
            float* c = acc[mb][idx];
            if (r0 < n) {
                __half2 p = __floats2half2_rn(c[0], c[1]);
                *(u32*)&g_h1[(size_t)r0 * HID + col] = *(u32*)&p;
            }
            if (r1 < n) {
                __half2 p = __floats2half2_rn(c[2], c[3]);
                *(u32*)&g_h1[(size_t)r1 * HID + col] = *(u32*)&p;
            }
        }
    }
}

// ------------------------------------------------- layer1 CSR aggregation ---
// Warp per node, half-warp edge split, 8 edges in flight per half (MLP=8).
// (R15 version — flat batching; compiler front-batches the loads.)
__global__ void k_agg1(const float* __restrict__ b1, int n) {
    int gid = blockIdx.x * blockDim.x + threadIdx.x;
    int node = gid >> 5;
    int lane = threadIdx.x & 31;
    if (node >= n) return;
    int half = lane >> 4, fl = lane & 15;

    const uint4* h1 = (const uint4*)g_h1;
    float acc[8] = {};
    int beg = g_rowstart[node];
    int end = g_rowstart[node + 1];
    #define ACC_E(uu, qq) { \
        float2 a0 = __half22float2(*(__half2*)&uu.x); \
        float2 a1_ = __half22float2(*(__half2*)&uu.y); \
        float2 a2 = __half22float2(*(__half2*)&uu.z); \
        float2 a3 = __half22float2(*(__half2*)&uu.w); \
        acc[0] = fmaf(qq, a0.x, acc[0]); acc[1] = fmaf(qq, a0.y, acc[1]); \
        acc[2] = fmaf(qq, a1_.x, acc[2]); acc[3] = fmaf(qq, a1_.y, acc[3]); \
        acc[4] = fmaf(qq, a2.x, acc[4]); acc[5] = fmaf(qq, a2.y, acc[5]); \
        acc[6] = fmaf(qq, a3.x, acc[6]); acc[7] = fmaf(qq, a3.y, acc[7]); }
    int j = beg + half;
    for (; j + 14 < end; j += 16) {      // 8 edges per half in flight
        int s[8];
        #pragma unroll
        for (int t = 0; t < 8; t++) s[t] = g_elist[j + 2 * t];
        float q[8];
        #pragma unroll
        for (int t = 0; t < 8; t++) q[t] = __ldg(&g_isd[s[t]]);
        uint4 u[8];
        #pragma unroll
        for (int t = 0; t < 8; t++) u[t] = h1[(size_t)s[t] * 16 + fl];
        #pragma unroll
        for (int t = 0; t < 8; t++) ACC_E(u[t], q[t])
    }
    for (; j < end; j += 2) {
        int s = g_elist[j];
        float q = __ldg(&g_isd[s]);
        uint4 uu = h1[(size_t)s * 16 + fl];
        ACC_E(uu, q)
    }
    #undef ACC_E
    #pragma unroll
    for (int t = 0; t < 8; t++)
        acc[t] += __shfl_xor_sync(0xffffffffu, acc[t], 16);

    if (half == 0) {
        float sd = g_isd[node];
        float4 blo = *(const float4*)&b1[fl * 8];
        float4 bhi = *(const float4*)&b1[fl * 8 + 4];
        float o0 = fmaxf(fmaf(sd, acc[0], blo.x), 0.f);
        float o1 = fmaxf(fmaf(sd, acc[1], blo.y), 0.f);
        float o2 = fmaxf(fmaf(sd, acc[2], blo.z), 0.f);
        float o3 = fmaxf(fmaf(sd, acc[3], blo.w), 0.f);
        float o4 = fmaxf(fmaf(sd, acc[4], bhi.x), 0.f);
        float o5 = fmaxf(fmaf(sd, acc[5], bhi.y), 0.f);
        float o6 = fmaxf(fmaf(sd, acc[6], bhi.z), 0.f);
        float o7 = fmaxf(fmaf(sd, acc[7], bhi.w), 0.f);
        __half2 p0 = __floats2half2_rn(o0, o1);
        __half2 p1 = __floats2half2_rn(o2, o3);
        __half2 p2 = __floats2half2_rn(o4, o5);
        __half2 p3 = __floats2half2_rn(o6, o7);
        uint4 outv = make_uint4(*(u32*)&p0, *(u32*)&p1, *(u32*)&p2, *(u32*)&p3);
        ((uint4*)g_a1)[(size_t)node * 16 + fl] = outv;
    }
}

// -------------------------------------------------------------- HMMA GEMM2 --
#define G2_SA    0            // 2 chunks x 16384
#define G2_BH    32768        // 2 chunks x 6144
#define G2_BL    45056        // 2 chunks x 6144
#define SMEM_G2  57344

__global__ void __launch_bounds__(256)
k_gemm2(int n) {
    extern __shared__ char smem[];
    u32 sb;
    asm("{ .reg .u64 t; cvta.to.shared.u64 t, %1; cvt.u32.u64 %0, t; }"
        : "=r"(sb) : "l"(smem));
    const int tid = threadIdx.x;
    const int l = tid & 31;
    const int wm = tid >> 5;
    const int m0 = blockIdx.x * 128;

    #pragma unroll
    for (int j = 0; j < 8; j++) {
        int u = tid + j * 256;
        int r = u >> 4, k8 = (u & 15) * 8;
        int ch = k8 >> 6, w = k8 & 63;
        int row = m0 + r;
        uint4 v = make_uint4(0, 0, 0, 0);
        if (row < n) v = *(const uint4*)&g_a1[(size_t)row * HID + k8];
        *(uint4*)(smem + G2_SA + ch * 16384 + toff(r, w * 2)) = v;
    }
    #pragma unroll
    for (int j = 0; j < 3; j++) {
        int u = tid + j * 256;
        int r = u >> 4, k8 = (u & 15) * 8;
        int ch = k8 >> 6, w = k8 & 63;
        uint4 vh = make_uint4(0, 0, 0, 0), vl = make_uint4(0, 0, 0, 0);
        if (r < OUT_DIM) {
            vh = *(const uint4*)&g_W2h[r * HID + k8];
            vl = *(const uint4*)&g_W2l[r * HID + k8];
        }
        u32 off = toff(r, w * 2);
        *(uint4*)(smem + G2_BH + ch * 6144 + off) = vh;
        *(uint4*)(smem + G2_BL + ch * 6144 + off) = vl;
    }
    __syncthreads();

    float acc[3][8] = {};

    u32 PA, XA;
    {
        int r = wm * 16 + (l & 7) + 8 * ((l >> 3) & 1);
        PA = (u32)((r >> 3) * 1024 + (r & 7) * 128);
        XA = (u32)((r & 7) << 4);
    }
    u32 cblA = 16 * (l >> 4);
    u32 PB[3], XB[3];
    #pragma unroll
    for (int nt = 0; nt < 3; nt++) {
        int r = nt * 16 + (l & 7) + 8 * ((l >> 4) & 1);
        PB[nt] = (u32)((r >> 3) * 1024 + (r & 7) * 128);
        XB[nt] = (u32)((r & 7) << 4);
    }
    u32 cblB = 16 * ((l >> 3) & 1);

    #pragma unroll
    for (int ch = 0; ch < 2; ch++) {
        u32 baseA = sb + G2_SA + ch * 16384;
        u32 baseBh = sb + G2_BH + ch * 6144;
        u32 baseBl = sb + G2_BL + ch * 6144;
        #pragma unroll
        for (int ks = 0; ks < 4; ks++) {
            u32 kb = ks * 32;
            u32 Af[4], Bh[3][4], Bl[3][4];
            ldsm4(Af, baseA + PA + ((kb + cblA) ^ XA));
            #pragma unroll
            for (int nt = 0; nt < 3; nt++) {
                u32 boff = PB[nt] + ((kb + cblB) ^ XB[nt]);
                ldsm4(Bh[nt], baseBh + boff);
                ldsm4(Bl[nt], baseBl + boff);
            }
            #pragma unroll
            for (int nt = 0; nt < 3; nt++)
                #pragma unroll
                for (int j = 0; j < 2; j++) {
                    float* c = &acc[nt][4 * j];
                    mma16816(c, Af, &Bh[nt][2 * j]);
                    mma16816(c, Af, &Bl[nt][2 * j]);
                }
        }
    }

    int r0 = m0 + wm * 16 + (l >> 2);
    int r1 = r0 + 8;
    float s0 = (r0 < n) ? g_isd[r0] : 0.f;
    float s1 = (r1 < n) ? g_isd[r1] : 0.f;
    #pragma unroll
    for (int nt = 0; nt < 3; nt++)
        #pragma unroll
        for (int j = 0; j < 2; j++) {
            int col = nt * 16 + j * 8 + (l & 3) * 2;
            if (col < OUT_DIM) {
                float* c = &acc[nt][4 * j];
                if (r0 < n) {
                    __half2 p = __floats2half2_rn(c[0] * s0, c[1] * s0);
                    *(u32*)&g_h2[(size_t)r0 * OUT_DIM + col] = *(u32*)&p;
                }
                if (r1 < n) {
                    __half2 p = __floats2half2_rn(c[2] * s1, c[3] * s1);
                    *(u32*)&g_h2[(size_t)r1 * OUT_DIM + col] = *(u32*)&p;
                }
            }
        }
}

// -------------------------------------------------- layer2 CSR aggregation --
// thread per (node, uint4-chunk c<5), 8 edges in flight (R15 version).
__global__ void k_agg2(const float* __restrict__ b2, float* __restrict__ out, int n) {
    int i = blockIdx.x * blockDim.x + threadIdx.x;
    if (i >= n * 5) return;
    int node = i / 5;
    int c = i - node * 5;
    int beg = g_rowstart[node];
    int end = g_rowstart[node + 1];
    const uint4* h2 = (const uint4*)g_h2;
    float acc[8] = {};
    #define ACC2(uu) { \
        float2 a0 = __half22float2(*(__half2*)&uu.x); \
        float2 a1_ = __half22float2(*(__half2*)&uu.y); \
        float2 a2 = __half22float2(*(__half2*)&uu.z); \
        float2 a3 = __half22float2(*(__half2*)&uu.w); \
        acc[0] += a0.x; acc[1] += a0.y; acc[2] += a1_.x; acc[3] += a1_.y; \
        acc[4] += a2.x; acc[5] += a2.y; acc[6] += a3.x; acc[7] += a3.y; }
    int j = beg;
    for (; j + 8 <= end; j += 8) {
        int s[8];
        #pragma unroll
        for (int t = 0; t < 8; t++) s[t] = g_elist[j + t];
        uint4 u[8];
        #pragma unroll
        for (int t = 0; t < 8; t++) u[t] = h2[(size_t)s[t] * 5 + c];
        #pragma unroll
        for (int t = 0; t < 8; t++) ACC2(u[t])
    }
    for (; j < end; j++) {
        int s = g_elist[j];
        uint4 uu = h2[(size_t)s * 5 + c];
        ACC2(uu)
    }
    #undef ACC2
    float sd = g_isd[node];
    float4 blo = *(const float4*)&b2[c * 8];
    float4 bhi = *(const float4*)&b2[c * 8 + 4];
    float* o = &out[(size_t)node * OUT_DIM + c * 8];
    *(float4*)&o[0] = make_float4(fmaf(sd, acc[0], blo.x), fmaf(sd, acc[1], blo.y),
                                  fmaf(sd, acc[2], blo.z), fmaf(sd, acc[3], blo.w));
    *(float4*)&o[4] = make_float4(fmaf(sd, acc[4], bhi.x), fmaf(sd, acc[5], bhi.y),
                                  fmaf(sd, acc[6], bhi.z), fmaf(sd, acc[7], bhi.w));
}

// ---------------------------------------------------------------- launch ----
extern "C" void kernel_launch(void* const* d_in, const int* in_sizes, int n_in,
                              void* d_out, int out_size) {
    const float* x   = (const float*)d_in[0];
    const int*   src = (const int*)d_in[1];
    const int*   dst = (const int*)d_in[2];
    const float* W1  = (const float*)d_in[3];
    const float* b1  = (const float*)d_in[4];
    const float* W2  = (const float*)d_in[5];
    const float* b2  = (const float*)d_in[6];
    float* out = (float*)d_out;

    int n = in_sizes[0] / IN_DIM;
    int e = in_sizes[1];

    static cudaStream_t s_side = 0;
    static cudaEvent_t e_fork = 0, e_join = 0;
    if (!s_side) {
        cudaFuncSetAttribute(k_gemm1, cudaFuncAttributeMaxDynamicSharedMemorySize,
                             SMEM_G1);
        cudaFuncSetAttribute(k_gemm2, cudaFuncAttributeMaxDynamicSharedMemorySize,
                             SMEM_G2);
        cudaStreamCreateWithFlags(&s_side, cudaStreamNonBlocking);
        cudaEventCreateWithFlags(&e_fork, cudaEventDisableTiming);
        cudaEventCreateWithFlags(&e_join, cudaEventDisableTiming);
    }

    // k_gemm1 stays the 4th submission (ncu -s 5 -c 1 captures it).
    k_splitW<<<(HID * IN_DIM + 255) / 256, 256>>>(W1, W2);          // 1 (main)

    cudaEventRecord(e_fork, 0);
    cudaStreamWaitEvent(s_side, e_fork, 0);
    k_zero_deg<<<(n + 255) / 256, 256, 0, s_side>>>(n);             // 2
    k_count<<<(e + 255) / 256, 256, 0, s_side>>>(dst, e);           // 3

    k_gemm1<<<(n + 127) / 128, 256, SMEM_G1>>>(x, n);               // 4 (main)

    k_scan1<<<NB_SCAN, SCAN_BS, 0, s_side>>>(n);                    // 5 (+isd)
    k_scan2<<<1, 32, 0, s_side>>>(n, e);                            // 6
    k_scan3<<<(n + 255) / 256, 256, 0, s_side>>>(n);                // 7
    k_scatter<<<(e + 255) / 256, 256, 0, s_side>>>(src, dst, e);    // 8
    cudaEventRecord(e_join, s_side);

    cudaStreamWaitEvent(0, e_join, 0);
    k_agg1<<<((n * 32) + 255) / 256, 256>>>(b1, n);                 // 9
    k_gemm2<<<(n + 127) / 128, 256, SMEM_G2>>>(n);                  // 10
    k_agg2<<<(n * 5 + 255) / 256, 256>>>(b2, out, n);               // 11
}